// round 14
// baseline (speedup 1.0000x reference)
#include <cuda_runtime.h>
#include <cuda_fp16.h>

#define NN 20000
#define EE 320000
#define PAD 20480              // padded per-relation segment count (80 * 256)
#define NSEG (4 * PAD)         // 81920 total segments
#define GMB 313                // GEMM M-blocks (64 rows each)

constexpr size_t S_NN   = (size_t)NN * 128;
constexpr size_t OFF_Q    = 0;                          // q_a, q_b           : 2*S_NN fp32
constexpr size_t OFF_K    = OFF_Q   + 2 * S_NN;         // k per relation fp16 (4 rel)
constexpr size_t OFF_V    = OFF_K   + 2 * S_NN;         // v per relation fp16
constexpr size_t OFF_SRT  = OFF_V   + 2 * S_NN;         // sorted src ids     : 4*EE
constexpr size_t OFF_OFFS = OFF_SRT + (size_t)4 * EE;   // segment offsets    : NSEG
constexpr size_t OFF_CUR  = OFF_OFFS + NSEG;            // scatter cursors    : NSEG
constexpr size_t OFF_BLK  = OFF_CUR  + NSEG;            // block partials     : 128
constexpr size_t OFF_CNT  = OFF_BLK  + 128;             // histogram          : NSEG
constexpr size_t OFF_AGG  = OFF_CNT  + NSEG;            // aggregates (a,b)   : 2*S_NN
constexpr size_t OFF_WS   = OFF_AGG + 2 * S_NN;         // preswizzled fp16 hi/lo W
constexpr size_t OFF_AP   = OFF_WS + (size_t)8 * 8 * 2048;  // preswizzled fp16 hi/lo A
constexpr size_t TOTAL    = OFF_AP + (size_t)2 * GMB * 8 * 1024;

__device__ __align__(256) float g_s[TOTAL];

typedef unsigned long long u64;
typedef unsigned int u32;

// dynamic smem layout (bytes)
#define AH_OFF 0
#define AL_OFF 2048
#define BH_OFF 4096
#define BL_OFF 8192
#define CS_OFF 12288           // 64 x 132 fp32 = 33792
#define RS_OFF 46080           // 2 x 2048 fp32 = 16384
#define SMEM_SZ 62464

__device__ __forceinline__ u64 pk2(float x) {
    u64 r; asm("mov.b64 %0, {%1, %1};" : "=l"(r) : "f"(x)); return r;
}
__device__ __forceinline__ void fma2(u64& d, u64 a, u64 b) {
    asm("fma.rn.f32x2 %0, %1, %2, %0;" : "+l"(d) : "l"(a), "l"(b));
}
__device__ __forceinline__ float2 up2(u64 v) {
    float2 f; asm("mov.b64 {%0, %1}, %2;" : "=f"(f.x), "=f"(f.y) : "l"(v)); return f;
}
__device__ __forceinline__ void mma16(float* c, const u32* a, const u32* b) {
    asm("mma.sync.aligned.m16n8k16.row.col.f32.f16.f16.f32 "
        "{%0,%1,%2,%3}, {%4,%5,%6,%7}, {%8,%9}, {%0,%1,%2,%3};"
        : "+f"(c[0]), "+f"(c[1]), "+f"(c[2]), "+f"(c[3])
        : "r"(a[0]), "r"(a[1]), "r"(a[2]), "r"(a[3]), "r"(b[0]), "r"(b[1]));
}

struct Edges { const int* src[4]; const int* dst[4]; };

struct GemmBatch {
    const float* A[6];        // used when atype < 0 (in-kernel split)
    int          atype[6];    // 0 = h_a pre, 1 = h_b pre, -1 = in-kernel
    int          wm[6];       // preswizzled weight index
    int          md[6];       // 0 = plain, 1 = skip-epilogue, 2 = relation-transform
    const float* bias[6];
    float*       C[6];        // modes 0/1
    const float* hres[6];     // mode 1
    const float* rel2[6];     // mode 2: rel base for relations r0, r0+1
    __half*      hout[6];     // mode 2: fp16 out base for relation r0
};

// ---------------------------------------------------------------------------
// One-shot weight preconversion (fp16 hi/lo, m16n8k16 fragment layout).
// ---------------------------------------------------------------------------
__global__ __launch_bounds__(256) void wprep_kernel(
    const float* __restrict__ Wk, const float* __restrict__ Wq,
    const float* __restrict__ Wv, const float* __restrict__ Wa)
{
    const float* mats[8] = {Wk, Wk + 16384, Wq, Wq + 16384,
                            Wv, Wv + 16384, Wa, Wa + 16384};
    int mat = blockIdx.x, kc = blockIdx.y;
    const float* W = mats[mat];
    u32* dstH = (u32*)&g_s[OFF_WS] + (size_t)(mat * 8 + kc) * 2048;
    u32* dstL = dstH + 1024;

    int t = threadIdx.x;
    int bk = t >> 4;
    int bn8 = (t & 15) * 8;
    const float* wr = &W[(size_t)(kc * 16 + bk) * 128 + bn8];
    float4 w0 = *(const float4*)&wr[0];
    float4 w1 = *(const float4*)&wr[4];
    float wv[8] = {w0.x, w0.y, w0.z, w0.w, w1.x, w1.y, w1.z, w1.w};
    int c = (bk & 7) >> 1, hlf = bk & 1, reg = bk >> 3;
#pragma unroll
    for (int j = 0; j < 8; j++) {
        int n = bn8 + j;
        int wn = n >> 5, nt = (n >> 3) & 3, g = n & 7;
        int idx = nt * 2 + reg;
        int lane = g * 4 + c;
        int flat = wn * 256 + (idx >> 2) * 128 + lane * 4 + (idx & 3);
        float x = wv[j];
        __half hi = __float2half_rn(x);
        float lo = x - __half2float(hi);
        ((__half*)dstH)[flat * 2 + hlf] = hi;
        ((__half*)dstL)[flat * 2 + hlf] = __float2half_rn(lo);
    }
}

// ---------------------------------------------------------------------------
// One-shot A preconversion: h_a / h_b split to fp16 hi/lo in fragment layout.
// ---------------------------------------------------------------------------
__global__ __launch_bounds__(256) void aprep_kernel(
    const float* __restrict__ h_a, const float* __restrict__ h_b)
{
    __shared__ u32 buf[1024];
    int type = blockIdx.z, blk = blockIdx.x, kc = blockIdx.y;
    const float* src = type ? h_b : h_a;
    int t = threadIdx.x;
    int ar = t >> 2;
    int ac4 = (t & 3) * 4;
    int row = blk * 64 + ar;
    float4 va;
    if (row < NN) va = *(const float4*)&src[(size_t)row * 128 + kc * 16 + ac4];
    else          va = make_float4(0.f, 0.f, 0.f, 0.f);

    int awm = ar >> 5, amt = (ar >> 4) & 1, arh = (ar >> 3) & 1, agg = ar & 7;
    int khigh = ac4 >> 3, c0 = (ac4 & 7) >> 1;
    int areg = khigh * 2 + arh;
    int aidx = amt * 4 + areg;
    int lane0 = agg * 4 + c0;
    int f0 = awm * 256 + (aidx >> 2) * 128 + lane0 * 4 + (aidx & 3);
    int f1 = f0 + 4;

    __half2 h0 = __floats2half2_rn(va.x, va.y);
    float2 d0 = __half22float2(h0);
    __half2 l0 = __floats2half2_rn(va.x - d0.x, va.y - d0.y);
    __half2 h1 = __floats2half2_rn(va.z, va.w);
    float2 d1 = __half22float2(h1);
    __half2 l1 = __floats2half2_rn(va.z - d1.x, va.w - d1.y);
    buf[f0]       = *(u32*)&h0;
    buf[f1]       = *(u32*)&h1;
    buf[512 + f0] = *(u32*)&l0;
    buf[512 + f1] = *(u32*)&l1;
    __syncthreads();
    u32* dst = (u32*)&g_s[OFF_AP] + (((size_t)type * GMB + blk) * 8 + kc) * 1024;
    *(uint4*)&dst[t * 4] = *(const uint4*)&buf[t * 4];
}

// ---------------------------------------------------------------------------
// Tensor-core (M x 128)@(128 x 128) GEMM, 2-term fp16 compensation.
// (identical to R13-verified version)
// ---------------------------------------------------------------------------
__global__ __launch_bounds__(256, 2) void gemm_tc(
    GemmBatch gb, int M, const float* __restrict__ skip)
{
    extern __shared__ char smd[];
    u32* AhF = (u32*)(smd + AH_OFF);
    u32* AlF = (u32*)(smd + AL_OFF);
    u32* BhF = (u32*)(smd + BH_OFF);
    u32* BlF = (u32*)(smd + BL_OFF);

    int b = blockIdx.y;
    int md    = gb.md[b];
    int atype = gb.atype[b];
    const float* __restrict__ bias = gb.bias[b];
    const u32*   __restrict__ Wsw  = (const u32*)&g_s[OFF_WS] +
                                     (size_t)gb.wm[b] * 8 * 2048;
    const u32*   __restrict__ Apre = (const u32*)&g_s[OFF_AP];

    int t    = threadIdx.x;
    int m0   = blockIdx.x * 64;
    int wid  = t >> 5;
    int lane = t & 31;
    int wm   = wid >> 2;
    int wn   = wid & 3;
    int g    = lane >> 2;
    int c    = lane & 3;

    float cf[2][4][4];
#pragma unroll
    for (int mt = 0; mt < 2; mt++)
#pragma unroll
        for (int nt = 0; nt < 4; nt++)
#pragma unroll
            for (int i = 0; i < 4; i++) cf[mt][nt][i] = 0.f;

    int ar = t >> 2;
    int ac4 = (t & 3) * 4;
    int t4 = t * 4;
    int awm = ar >> 5, amt = (ar >> 4) & 1, arh = (ar >> 3) & 1, agg = ar & 7;
    int khigh = ac4 >> 3, c0i = (ac4 & 7) >> 1;
    int areg = khigh * 2 + arh;
    int aidx = amt * 4 + areg;
    int fl0 = awm * 256 + (aidx >> 2) * 128 + (agg * 4 + c0i) * 4 + (aidx & 3);
    int fl1 = fl0 + 4;

    for (int kc = 0; kc < 8; kc++) {
        if (atype >= 0) {
            const u32* sA = Apre + (((size_t)atype * GMB + blockIdx.x) * 8 + kc) * 1024;
            *(uint2*)&AhF[t * 2] = *(const uint2*)&sA[t * 2];
            *(uint2*)&AlF[t * 2] = *(const uint2*)&sA[512 + t * 2];
        } else {
            const float* A = gb.A[b];
            float4 va;
            if (m0 + ar < M) va = *(const float4*)&A[(size_t)(m0 + ar) * 128 + kc * 16 + ac4];
            else             va = make_float4(0.f, 0.f, 0.f, 0.f);
            __half2 h0 = __floats2half2_rn(va.x, va.y);
            float2 d0 = __half22float2(h0);
            __half2 l0 = __floats2half2_rn(va.x - d0.x, va.y - d0.y);
            __half2 h1 = __floats2half2_rn(va.z, va.w);
            float2 d1 = __half22float2(h1);
            __half2 l1 = __floats2half2_rn(va.z - d1.x, va.w - d1.y);
            AhF[fl0] = *(u32*)&h0;
            AhF[fl1] = *(u32*)&h1;
            AlF[fl0] = *(u32*)&l0;
            AlF[fl1] = *(u32*)&l1;
        }
        {
            const u32* srcH = Wsw + (size_t)kc * 2048;
            const u32* srcL = srcH + 1024;
            *(uint4*)&BhF[t4] = *(const uint4*)&srcH[t4];
            *(uint4*)&BlF[t4] = *(const uint4*)&srcL[t4];
        }
        __syncthreads();

        {
            u32 uah[8], ual[8], ubh[8], ubl[8];
            *(uint4*)&uah[0] = *(const uint4*)&AhF[wm * 256 + lane * 4];
            *(uint4*)&uah[4] = *(const uint4*)&AhF[wm * 256 + 128 + lane * 4];
            *(uint4*)&ual[0] = *(const uint4*)&AlF[wm * 256 + lane * 4];
            *(uint4*)&ual[4] = *(const uint4*)&AlF[wm * 256 + 128 + lane * 4];
            *(uint4*)&ubh[0] = *(const uint4*)&BhF[wn * 256 + lane * 4];
            *(uint4*)&ubh[4] = *(const uint4*)&BhF[wn * 256 + 128 + lane * 4];
            *(uint4*)&ubl[0] = *(const uint4*)&BlF[wn * 256 + lane * 4];
            *(uint4*)&ubl[4] = *(const uint4*)&BlF[wn * 256 + 128 + lane * 4];
#pragma unroll
            for (int mt = 0; mt < 2; mt++)
#pragma unroll
                for (int nt = 0; nt < 4; nt++) {
                    mma16(cf[mt][nt], &uah[mt * 4], &ubh[nt * 2]);
                    mma16(cf[mt][nt], &uah[mt * 4], &ubl[nt * 2]);
                    mma16(cf[mt][nt], &ual[mt * 4], &ubh[nt * 2]);
                }
        }
        __syncthreads();
    }

    if (md == 2) {
        float* Csm   = (float*)(smd + CS_OFF);   // [64][132]
        float* rel_s = (float*)(smd + RS_OFF);   // [2][2048]
        const float* rel2 = gb.rel2[b];
        for (int i = t; i < 4096; i += 256) rel_s[i] = rel2[i];
#pragma unroll
        for (int mt = 0; mt < 2; mt++)
#pragma unroll
            for (int half = 0; half < 2; half++) {
                int rl = wm * 32 + mt * 16 + half * 8 + g;
#pragma unroll
                for (int nt = 0; nt < 4; nt++) {
                    int col = wn * 32 + nt * 8 + c * 2;
                    float2 bb = *(const float2*)&bias[col];
                    Csm[rl * 132 + col]     = cf[mt][nt][half * 2 + 0] + bb.x;
                    Csm[rl * 132 + col + 1] = cf[mt][nt][half * 2 + 1] + bb.y;
                }
            }
        __syncthreads();

        int o2 = t & 63;
        int h = o2 >> 3, ep = (o2 & 7) * 2;
        __half* hout = gb.hout[b];
        const float* rb0 = &rel_s[h * 256 + ep];
        const float* rb1 = &rel_s[2048 + h * 256 + ep];
#pragma unroll 1
        for (int i = 0; i < 16; i++) {
            int nl = (t >> 6) + i * 4;
            int node = m0 + nl;
            if (node >= M) continue;
            const float* crow = &Csm[nl * 132 + h * 16];
            float4 c0 = *(const float4*)&crow[0];
            float4 c1 = *(const float4*)&crow[4];
            float4 c2 = *(const float4*)&crow[8];
            float4 c3 = *(const float4*)&crow[12];
#pragma unroll
            for (int ri = 0; ri < 2; ri++) {
                const float* rs = ri ? rb1 : rb0;
                u64 acc = 0ull;
                fma2(acc, pk2(c0.x), *(const u64*)&rs[0]);
                fma2(acc, pk2(c0.y), *(const u64*)&rs[16]);
                fma2(acc, pk2(c0.z), *(const u64*)&rs[32]);
                fma2(acc, pk2(c0.w), *(const u64*)&rs[48]);
                fma2(acc, pk2(c1.x), *(const u64*)&rs[64]);
                fma2(acc, pk2(c1.y), *(const u64*)&rs[80]);
                fma2(acc, pk2(c1.z), *(const u64*)&rs[96]);
                fma2(acc, pk2(c1.w), *(const u64*)&rs[112]);
                fma2(acc, pk2(c2.x), *(const u64*)&rs[128]);
                fma2(acc, pk2(c2.y), *(const u64*)&rs[144]);
                fma2(acc, pk2(c2.z), *(const u64*)&rs[160]);
                fma2(acc, pk2(c2.w), *(const u64*)&rs[176]);
                fma2(acc, pk2(c3.x), *(const u64*)&rs[192]);
                fma2(acc, pk2(c3.y), *(const u64*)&rs[208]);
                fma2(acc, pk2(c3.z), *(const u64*)&rs[224]);
                fma2(acc, pk2(c3.w), *(const u64*)&rs[240]);
                float2 res = up2(acc);
                *(__half2*)(hout + ((size_t)ri * NN + node) * 128 + h * 16 + ep) =
                    __floats2half2_rn(res.x, res.y);
            }
        }
        return;
    }

    float* C = gb.C[b];
    float al = 0.f, om = 0.f;
    if (md == 1) { al = 1.f / (1.f + __expf(-skip[b])); om = 1.f - al; }

#pragma unroll
    for (int mt = 0; mt < 2; mt++) {
        int rbase = m0 + wm * 32 + mt * 16 + g;
#pragma unroll
        for (int half = 0; half < 2; half++) {
            int row = rbase + half * 8;
            if (row >= M) continue;
#pragma unroll
            for (int nt = 0; nt < 4; nt++) {
                int col = wn * 32 + nt * 8 + c * 2;
                float v0 = cf[mt][nt][half * 2 + 0];
                float v1 = cf[mt][nt][half * 2 + 1];
                float2 bb = *(const float2*)&bias[col];
                float2 o;
                if (md == 0) {
                    o.x = v0 + bb.x; o.y = v1 + bb.y;
                } else {
                    float2 hr = *(const float2*)&gb.hres[b][(size_t)row * 128 + col];
                    o.x = al * (0.5f * v0 + bb.x) + om * hr.x;
                    o.y = al * (0.5f * v1 + bb.y) + om * hr.y;
                }
                *(float2*)&C[(size_t)row * 128 + col] = o;
            }
        }
    }
}

// ---------------------------------------------------------------------------
// Counting sort of edges by (relation, dst)
// ---------------------------------------------------------------------------
__global__ __launch_bounds__(256) void hist_kernel(Edges eg)
{
    int r = blockIdx.y;
    int e = blockIdx.x * 256 + threadIdx.x;
    int d = eg.dst[r][e];
    atomicAdd((int*)&g_s[OFF_CNT] + r * PAD + d, 1);
}

__global__ __launch_bounds__(256) void scanA_kernel()
{
    const int* cnt  = (const int*)&g_s[OFF_CNT];
    int*       offs = (int*)&g_s[OFF_OFFS];
    int*       blk  = (int*)&g_s[OFF_BLK];
    __shared__ int sm[256];
    int t = threadIdx.x;
    int base = (blockIdx.x * 256 + t) * 4;
    int c0 = cnt[base], c1 = cnt[base + 1], c2 = cnt[base + 2], c3 = cnt[base + 3];
    int tot = c0 + c1 + c2 + c3;
    sm[t] = tot;
    __syncthreads();
#pragma unroll
    for (int off = 1; off < 256; off <<= 1) {
        int u = (t >= off) ? sm[t - off] : 0;
        __syncthreads();
        sm[t] += u;
        __syncthreads();
    }
    int ex = sm[t] - tot;
    offs[base]     = ex;
    offs[base + 1] = ex + c0;
    offs[base + 2] = ex + c0 + c1;
    offs[base + 3] = ex + c0 + c1 + c2;
    if (t == 255) blk[blockIdx.x] = sm[255];
}

__global__ __launch_bounds__(256) void scanC_kernel()
{
    int* offs = (int*)&g_s[OFF_OFFS];
    int* cur  = (int*)&g_s[OFF_CUR];
    const int* blk = (const int*)&g_s[OFF_BLK];
    __shared__ int pre[128];
    int t = threadIdx.x;
    if (t < 128) pre[t] = (t < 80) ? blk[t] : 0;
    __syncthreads();
#pragma unroll
    for (int off = 1; off < 128; off <<= 1) {
        int u = (t < 128 && t >= off) ? pre[t - off] : 0;
        __syncthreads();
        if (t < 128) pre[t] += u;
        __syncthreads();
    }
    int i = blockIdx.x * 256 + t;
    int bidx = i >> 10;
    int add = (bidx == 0) ? 0 : pre[bidx - 1];
    int v = offs[i] + add;
    offs[i] = v;
    cur[i]  = v;
}

__global__ __launch_bounds__(256) void scatter_kernel(Edges eg)
{
    int r = blockIdx.y;
    int e = blockIdx.x * 256 + threadIdx.x;
    int d = eg.dst[r][e];
    int pos = atomicAdd((int*)&g_s[OFF_CUR] + r * PAD + d, 1);
    ((int*)&g_s[OFF_SRT])[pos] = eg.src[r][e];
}

// ---------------------------------------------------------------------------
// Fused score + softmax + aggregate. One warp per (dst-type, node).
// Quarter-warp per edge (sub = lane>>3), lane owns one full head (hd = lane&7):
// no per-edge shuffles, 4 edges in flight; one xor-reduce per segment.
// ---------------------------------------------------------------------------
__global__ __launch_bounds__(256) void attn_kernel(const float* __restrict__ pri)
{
    int warp = (blockIdx.x * 256 + threadIdx.x) >> 5;
    int lane = threadIdx.x & 31;
    int sub  = lane >> 3;          // edge slot 0..3
    int hd   = lane & 7;           // head 0..7
    int dt = warp / PAD;
    int d  = warp - dt * PAD;
    if (d >= NN) return;
    const int* offs = (const int*)&g_s[OFF_OFFS];
    const int* ss   = (const int*)&g_s[OFF_SRT];

    // q for this head: 16 floats
    float q[16];
    {
        const float4* qp = (const float4*)&g_s[OFF_Q + ((size_t)dt * NN + d) * 128 + hd * 16];
        float4 a = qp[0], b2 = qp[1], c2 = qp[2], e2 = qp[3];
        q[0]=a.x;  q[1]=a.y;  q[2]=a.z;  q[3]=a.w;
        q[4]=b2.x; q[5]=b2.y; q[6]=b2.z; q[7]=b2.w;
        q[8]=c2.x; q[9]=c2.y; q[10]=c2.z; q[11]=c2.w;
        q[12]=e2.x; q[13]=e2.y; q[14]=e2.z; q[15]=e2.w;
    }
    float4 tot = make_float4(0.f, 0.f, 0.f, 0.f);

#pragma unroll
    for (int half = 0; half < 2; half++) {
        int r   = dt + half * 2;
        int seg = r * PAD + d;
        int beg = offs[seg];
        int end = offs[seg + 1];
        if (beg == end) continue;

        float ph = pri[r * 8 + hd] * 0.25f;
        const __half* kbase = (const __half*)&g_s[OFF_K] + (size_t)r * NN * 128;
        const __half* vbase = (const __half*)&g_s[OFF_V] + (size_t)r * NN * 128;

        float acc[16];
#pragma unroll
        for (int i = 0; i < 16; i++) acc[i] = 0.f;
        float ssum = 0.f;

        for (int c = beg; c < end; c += 4) {
            int m = end - c;
            bool valid = sub < m;
            int idx = c + (valid ? sub : m - 1);
            int s = ss[idx];
            const __half* kr = kbase + (size_t)s * 128 + hd * 16;
            const __half* vr = vbase + (size_t)s * 128 + hd * 16;
            uint4 k0 = *(const uint4*)kr;
            uint4 k1 = *(const uint4*)(kr + 8);
            uint4 v0 = *(const uint4*)vr;
            uint4 v1 = *(const uint4*)(vr + 8);

            float kf[16];
            {
                float2 f;
                f = __half22float2(*(__half2*)&k0.x); kf[0]=f.x; kf[1]=f.y;
                f = __half22float2(*(__half2*)&k0.y); kf[2]=f.x; kf[3]=f.y;
                f = __half22float2(*(__half2*)&k0.z); kf[4]=f.x; kf[5]=f.y;
                f = __half22float2(*(__half2*)&k0.w); kf[6]=f.x; kf[7]=f.y;
                f = __half22float2(*(__half2*)&k1.x); kf[8]=f.x; kf[9]=f.y;
                f = __half22float2(*(__half2*)&k1.y); kf[10]=f.x; kf[11]=f.y;
                f = __half22float2(*(__half2*)&k1.z); kf[12]=f.x; kf[13]=f.y;
                f = __half22float2(*(__half2*)&k1.w); kf[14]=f.x; kf[15]=f.y;
            }
            float dot = 0.f;
#pragma unroll
            for (int i = 0; i < 16; i++) dot = fmaf(kf[i], q[i], dot);

            float exv = valid ? __expf(dot * ph) : 0.f;
            ssum += exv;

            {
                float2 f;
                f = __half22float2(*(__half2*)&v0.x); acc[0]=fmaf(exv,f.x,acc[0]);   acc[1]=fmaf(exv,f.y,acc[1]);
                f = __half22float2(*(__half2*)&v0.y); acc[2]=fmaf(exv,f.x,acc[2]);   acc[3]=fmaf(exv,f.y,acc[3]);
                f = __half22float2(*(__half2*)&v0.z); acc[4]=fmaf(exv,f.x,acc[4]);   acc[5]=fmaf(exv,f.y,acc[5]);
                f = __half22float2(*(__half2*)&v0.w); acc[6]=fmaf(exv,f.x,acc[6]);   acc[7]=fmaf(exv,f.y,acc[7]);
                f = __half22float2(*(__half2*)&v1.x); acc[8]=fmaf(exv,f.x,acc[8]);   acc[9]=fmaf(exv,f.y,acc[9]);
                f = __half22float2(*(__half2*)&v1.y); acc[10]=fmaf(exv,f.x,acc[10]); acc[11]=fmaf(exv,f.y,acc[11]);
                f = __half22float2(*(__half2*)&v1.z); acc[12]=fmaf(exv,f.x,acc[12]); acc[13]=fmaf(exv,f.y,acc[13]);
                f = __half22float2(*(__half2*)&v1.w); acc[14]=fmaf(exv,f.x,acc[14]); acc[15]=fmaf(exv,f.y,acc[15]);
            }
        }

        // reduce over the 4 edge slots (lanes differing in bits 3,4)
#pragma unroll
        for (int off = 8; off <= 16; off <<= 1) {
            ssum += __shfl_xor_sync(0xffffffffu, ssum, off);
#pragma unroll
            for (int i = 0; i < 16; i++)
                acc[i] += __shfl_xor_sync(0xffffffffu, acc[i], off);
        }
        float inv = 1.f / ssum;
        float4 part;
        if      (sub == 0) part = make_float4(acc[0],  acc[1],  acc[2],  acc[3]);
        else if (sub == 1) part = make_float4(acc[4],  acc[5],  acc[6],  acc[7]);
        else if (sub == 2) part = make_float4(acc[8],  acc[9],  acc[10], acc[11]);
        else               part = make_float4(acc[12], acc[13], acc[14], acc[15]);
        tot.x = fmaf(part.x, inv, tot.x);
        tot.y = fmaf(part.y, inv, tot.y);
        tot.z = fmaf(part.z, inv, tot.z);
        tot.w = fmaf(part.w, inv, tot.w);
    }

    *(float4*)(&g_s[OFF_AGG + ((size_t)dt * NN + d) * 128 + hd * 16 + sub * 4]) = tot;
}

// ---------------------------------------------------------------------------
extern "C" void kernel_launch(void* const* d_in, const int* in_sizes, int n_in,
                              void* d_out, int out_size)
{
    const float* h_a  = (const float*)d_in[0];
    const float* h_b  = (const float*)d_in[1];
    const float* Wk   = (const float*)d_in[2];
    const float* bk   = (const float*)d_in[3];
    const float* Wq   = (const float*)d_in[4];
    const float* bq   = (const float*)d_in[5];
    const float* Wv   = (const float*)d_in[6];
    const float* bv   = (const float*)d_in[7];
    const float* Wa   = (const float*)d_in[8];
    const float* ba   = (const float*)d_in[9];
    const float* ratt = (const float*)d_in[10];
    const float* rmsg = (const float*)d_in[11];
    const float* rpri = (const float*)d_in[12];
    const float* skip = (const float*)d_in[13];
    float* out = (float*)d_out;

    float* base = nullptr;
    cudaGetSymbolAddress((void**)&base, g_s);
    __half* Kh = (__half*)(base + OFF_K);
    __half* Vh = (__half*)(base + OFF_V);

    cudaFuncSetAttribute(gemm_tc, cudaFuncAttributeMaxDynamicSharedMemorySize, SMEM_SZ);

    cudaMemsetAsync(base + OFF_CNT, 0, (size_t)NSEG * sizeof(int));

    Edges eg;
    eg.src[0] = (const int*)d_in[14]; eg.dst[0] = (const int*)d_in[15];
    eg.src[1] = (const int*)d_in[16]; eg.dst[1] = (const int*)d_in[17];
    eg.src[2] = (const int*)d_in[18]; eg.dst[2] = (const int*)d_in[19];
    eg.src[3] = (const int*)d_in[20]; eg.dst[3] = (const int*)d_in[21];

    // --- one-shot preconversions ---
    wprep_kernel<<<dim3(8, 8), 256>>>(Wk, Wq, Wv, Wa);
    aprep_kernel<<<dim3(GMB, 8, 2), 256>>>(h_a, h_b);

    // --- counting sort of edges by (rel, dst) ---
    dim3 egrid(EE / 256, 4);
    hist_kernel<<<egrid, 256>>>(eg);
    scanA_kernel<<<NSEG / 1024, 256>>>();
    scanC_kernel<<<NSEG / 256, 256>>>();
    scatter_kernel<<<egrid, 256>>>(eg);

    // --- batched projections: q (mode 0) + k/v with fused transform (mode 2) ---
    GemmBatch pj = {};
    pj.atype[0] = 0; pj.wm[0] = 2; pj.md[0] = 0; pj.bias[0] = bq;       pj.C[0] = base + OFF_Q;
    pj.atype[1] = 1; pj.wm[1] = 3; pj.md[1] = 0; pj.bias[1] = bq + 128; pj.C[1] = base + OFF_Q + S_NN;
    pj.atype[2] = 0; pj.wm[2] = 0; pj.md[2] = 2; pj.bias[2] = bk;       pj.rel2[2] = ratt;            pj.hout[2] = Kh;
    pj.atype[3] = 1; pj.wm[3] = 1; pj.md[3] = 2; pj.bias[3] = bk + 128; pj.rel2[3] = ratt + 2 * 2048; pj.hout[3] = Kh + (size_t)2 * NN * 128;
    pj.atype[4] = 0; pj.wm[4] = 4; pj.md[4] = 2; pj.bias[4] = bv;       pj.rel2[4] = rmsg;            pj.hout[4] = Vh;
    pj.atype[5] = 1; pj.wm[5] = 5; pj.md[5] = 2; pj.bias[5] = bv + 128; pj.rel2[5] = rmsg + 2 * 2048; pj.hout[5] = Vh + (size_t)2 * NN * 128;
    gemm_tc<<<dim3(GMB, 6), 256, SMEM_SZ>>>(pj, NN, nullptr);

    // --- fused score + softmax + aggregate ---
    attn_kernel<<<(2 * PAD) / 8, 256>>>(rpri);

    // --- batched output GEMMs with fused mean (0.5), bias, sigmoid skip ---
    GemmBatch og = {};
    og.A[0] = base + OFF_AGG;        og.atype[0] = -1; og.wm[0] = 6; og.md[0] = 1; og.bias[0] = ba;       og.C[0] = out;        og.hres[0] = h_a;
    og.A[1] = base + OFF_AGG + S_NN; og.atype[1] = -1; og.wm[1] = 7; og.md[1] = 1; og.bias[1] = ba + 128; og.C[1] = out + S_NN; og.hres[1] = h_b;
    gemm_tc<<<dim3(GMB, 2), 256, SMEM_SZ>>>(og, NN, skip);
}

// round 16
// speedup vs baseline: 1.4692x; 1.4692x over previous
#include <cuda_runtime.h>
#include <cuda_fp16.h>

#define NN 20000
#define EE 320000
#define PAD 20480              // padded per-relation segment count (80 * 256)
#define NSEG (4 * PAD)         // 81920 total segments
#define GMB 313                // GEMM M-blocks (64 rows each)

constexpr size_t S_NN   = (size_t)NN * 128;
constexpr size_t OFF_Q    = 0;                          // q_a, q_b           : 2*S_NN fp32
constexpr size_t OFF_K    = OFF_Q   + 2 * S_NN;         // k per relation fp16 (4 rel)
constexpr size_t OFF_V    = OFF_K   + 2 * S_NN;         // v per relation fp16
constexpr size_t OFF_SRT  = OFF_V   + 2 * S_NN;         // sorted src ids     : 4*EE
constexpr size_t OFF_OFFS = OFF_SRT + (size_t)4 * EE;   // segment offsets    : NSEG
constexpr size_t OFF_CUR  = OFF_OFFS + NSEG;            // scatter cursors    : NSEG
constexpr size_t OFF_BLK  = OFF_CUR  + NSEG;            // block partials     : 128
constexpr size_t OFF_CNT  = OFF_BLK  + 128;             // histogram          : NSEG
constexpr size_t OFF_AGG  = OFF_CNT  + NSEG;            // aggregates (a,b)   : 2*S_NN
constexpr size_t OFF_WS   = OFF_AGG + 2 * S_NN;         // preswizzled fp16 hi/lo W
constexpr size_t OFF_AP   = OFF_WS + (size_t)8 * 8 * 2048;  // preswizzled fp16 hi/lo A
constexpr size_t TOTAL    = OFF_AP + (size_t)2 * GMB * 8 * 1024;

__device__ __align__(256) float g_s[TOTAL];

typedef unsigned long long u64;
typedef unsigned int u32;

// dynamic smem layout (bytes)
#define AH_OFF 0
#define AL_OFF 2048
#define BH_OFF 4096
#define BL_OFF 8192
#define CS_OFF 12288           // 64 x 132 fp32 = 33792
#define RS_OFF 46080           // 2 x 2048 fp32 = 16384
#define SMEM_SZ 62464

__device__ __forceinline__ u64 pk2(float x) {
    u64 r; asm("mov.b64 %0, {%1, %1};" : "=l"(r) : "f"(x)); return r;
}
__device__ __forceinline__ void fma2(u64& d, u64 a, u64 b) {
    asm("fma.rn.f32x2 %0, %1, %2, %0;" : "+l"(d) : "l"(a), "l"(b));
}
__device__ __forceinline__ float2 up2(u64 v) {
    float2 f; asm("mov.b64 {%0, %1}, %2;" : "=f"(f.x), "=f"(f.y) : "l"(v)); return f;
}
__device__ __forceinline__ void mma16(float* c, const u32* a, const u32* b) {
    asm("mma.sync.aligned.m16n8k16.row.col.f32.f16.f16.f32 "
        "{%0,%1,%2,%3}, {%4,%5,%6,%7}, {%8,%9}, {%0,%1,%2,%3};"
        : "+f"(c[0]), "+f"(c[1]), "+f"(c[2]), "+f"(c[3])
        : "r"(a[0]), "r"(a[1]), "r"(a[2]), "r"(a[3]), "r"(b[0]), "r"(b[1]));
}

struct Edges { const int* src[4]; const int* dst[4]; };

struct GemmBatch {
    const float* A[6];        // used when atype < 0 (in-kernel split)
    int          atype[6];    // 0 = h_a pre, 1 = h_b pre, -1 = in-kernel
    int          wm[6];       // preswizzled weight index
    int          md[6];       // 0 = plain, 1 = skip-epilogue, 2 = relation-transform
    const float* bias[6];
    float*       C[6];        // modes 0/1
    const float* hres[6];     // mode 1
    const float* rel2[6];     // mode 2: rel base for relations r0, r0+1
    __half*      hout[6];     // mode 2: fp16 out base for relation r0
};

// ---------------------------------------------------------------------------
// One-shot weight preconversion (fp16 hi/lo, m16n8k16 fragment layout).
// ---------------------------------------------------------------------------
__global__ __launch_bounds__(256) void wprep_kernel(
    const float* __restrict__ Wk, const float* __restrict__ Wq,
    const float* __restrict__ Wv, const float* __restrict__ Wa)
{
    const float* mats[8] = {Wk, Wk + 16384, Wq, Wq + 16384,
                            Wv, Wv + 16384, Wa, Wa + 16384};
    int mat = blockIdx.x, kc = blockIdx.y;
    const float* W = mats[mat];
    u32* dstH = (u32*)&g_s[OFF_WS] + (size_t)(mat * 8 + kc) * 2048;
    u32* dstL = dstH + 1024;

    int t = threadIdx.x;
    int bk = t >> 4;
    int bn8 = (t & 15) * 8;
    const float* wr = &W[(size_t)(kc * 16 + bk) * 128 + bn8];
    float4 w0 = *(const float4*)&wr[0];
    float4 w1 = *(const float4*)&wr[4];
    float wv[8] = {w0.x, w0.y, w0.z, w0.w, w1.x, w1.y, w1.z, w1.w};
    int c = (bk & 7) >> 1, hlf = bk & 1, reg = bk >> 3;
#pragma unroll
    for (int j = 0; j < 8; j++) {
        int n = bn8 + j;
        int wn = n >> 5, nt = (n >> 3) & 3, g = n & 7;
        int idx = nt * 2 + reg;
        int lane = g * 4 + c;
        int flat = wn * 256 + (idx >> 2) * 128 + lane * 4 + (idx & 3);
        float x = wv[j];
        __half hi = __float2half_rn(x);
        float lo = x - __half2float(hi);
        ((__half*)dstH)[flat * 2 + hlf] = hi;
        ((__half*)dstL)[flat * 2 + hlf] = __float2half_rn(lo);
    }
}

// ---------------------------------------------------------------------------
// One-shot A preconversion: h_a / h_b split to fp16 hi/lo in fragment layout.
// ---------------------------------------------------------------------------
__global__ __launch_bounds__(256) void aprep_kernel(
    const float* __restrict__ h_a, const float* __restrict__ h_b)
{
    __shared__ u32 buf[1024];
    int type = blockIdx.z, blk = blockIdx.x, kc = blockIdx.y;
    const float* src = type ? h_b : h_a;
    int t = threadIdx.x;
    int ar = t >> 2;
    int ac4 = (t & 3) * 4;
    int row = blk * 64 + ar;
    float4 va;
    if (row < NN) va = *(const float4*)&src[(size_t)row * 128 + kc * 16 + ac4];
    else          va = make_float4(0.f, 0.f, 0.f, 0.f);

    int awm = ar >> 5, amt = (ar >> 4) & 1, arh = (ar >> 3) & 1, agg = ar & 7;
    int khigh = ac4 >> 3, c0 = (ac4 & 7) >> 1;
    int areg = khigh * 2 + arh;
    int aidx = amt * 4 + areg;
    int lane0 = agg * 4 + c0;
    int f0 = awm * 256 + (aidx >> 2) * 128 + lane0 * 4 + (aidx & 3);
    int f1 = f0 + 4;

    __half2 h0 = __floats2half2_rn(va.x, va.y);
    float2 d0 = __half22float2(h0);
    __half2 l0 = __floats2half2_rn(va.x - d0.x, va.y - d0.y);
    __half2 h1 = __floats2half2_rn(va.z, va.w);
    float2 d1 = __half22float2(h1);
    __half2 l1 = __floats2half2_rn(va.z - d1.x, va.w - d1.y);
    buf[f0]       = *(u32*)&h0;
    buf[f1]       = *(u32*)&h1;
    buf[512 + f0] = *(u32*)&l0;
    buf[512 + f1] = *(u32*)&l1;
    __syncthreads();
    u32* dst = (u32*)&g_s[OFF_AP] + (((size_t)type * GMB + blk) * 8 + kc) * 1024;
    *(uint4*)&dst[t * 4] = *(const uint4*)&buf[t * 4];
}

// ---------------------------------------------------------------------------
// Tensor-core (M x 128)@(128 x 128) GEMM, 2-term fp16 compensation.
// (identical to R13-verified version)
// ---------------------------------------------------------------------------
__global__ __launch_bounds__(256, 2) void gemm_tc(
    GemmBatch gb, int M, const float* __restrict__ skip)
{
    extern __shared__ char smd[];
    u32* AhF = (u32*)(smd + AH_OFF);
    u32* AlF = (u32*)(smd + AL_OFF);
    u32* BhF = (u32*)(smd + BH_OFF);
    u32* BlF = (u32*)(smd + BL_OFF);

    int b = blockIdx.y;
    int md    = gb.md[b];
    int atype = gb.atype[b];
    const float* __restrict__ bias = gb.bias[b];
    const u32*   __restrict__ Wsw  = (const u32*)&g_s[OFF_WS] +
                                     (size_t)gb.wm[b] * 8 * 2048;
    const u32*   __restrict__ Apre = (const u32*)&g_s[OFF_AP];

    int t    = threadIdx.x;
    int m0   = blockIdx.x * 64;
    int wid  = t >> 5;
    int lane = t & 31;
    int wm   = wid >> 2;
    int wn   = wid & 3;
    int g    = lane >> 2;
    int c    = lane & 3;

    float cf[2][4][4];
#pragma unroll
    for (int mt = 0; mt < 2; mt++)
#pragma unroll
        for (int nt = 0; nt < 4; nt++)
#pragma unroll
            for (int i = 0; i < 4; i++) cf[mt][nt][i] = 0.f;

    int ar = t >> 2;
    int ac4 = (t & 3) * 4;
    int t4 = t * 4;
    int awm = ar >> 5, amt = (ar >> 4) & 1, arh = (ar >> 3) & 1, agg = ar & 7;
    int khigh = ac4 >> 3, c0i = (ac4 & 7) >> 1;
    int areg = khigh * 2 + arh;
    int aidx = amt * 4 + areg;
    int fl0 = awm * 256 + (aidx >> 2) * 128 + (agg * 4 + c0i) * 4 + (aidx & 3);
    int fl1 = fl0 + 4;

    for (int kc = 0; kc < 8; kc++) {
        if (atype >= 0) {
            const u32* sA = Apre + (((size_t)atype * GMB + blockIdx.x) * 8 + kc) * 1024;
            *(uint2*)&AhF[t * 2] = *(const uint2*)&sA[t * 2];
            *(uint2*)&AlF[t * 2] = *(const uint2*)&sA[512 + t * 2];
        } else {
            const float* A = gb.A[b];
            float4 va;
            if (m0 + ar < M) va = *(const float4*)&A[(size_t)(m0 + ar) * 128 + kc * 16 + ac4];
            else             va = make_float4(0.f, 0.f, 0.f, 0.f);
            __half2 h0 = __floats2half2_rn(va.x, va.y);
            float2 d0 = __half22float2(h0);
            __half2 l0 = __floats2half2_rn(va.x - d0.x, va.y - d0.y);
            __half2 h1 = __floats2half2_rn(va.z, va.w);
            float2 d1 = __half22float2(h1);
            __half2 l1 = __floats2half2_rn(va.z - d1.x, va.w - d1.y);
            AhF[fl0] = *(u32*)&h0;
            AhF[fl1] = *(u32*)&h1;
            AlF[fl0] = *(u32*)&l0;
            AlF[fl1] = *(u32*)&l1;
        }
        {
            const u32* srcH = Wsw + (size_t)kc * 2048;
            const u32* srcL = srcH + 1024;
            *(uint4*)&BhF[t4] = *(const uint4*)&srcH[t4];
            *(uint4*)&BlF[t4] = *(const uint4*)&srcL[t4];
        }
        __syncthreads();

        {
            u32 uah[8], ual[8], ubh[8], ubl[8];
            *(uint4*)&uah[0] = *(const uint4*)&AhF[wm * 256 + lane * 4];
            *(uint4*)&uah[4] = *(const uint4*)&AhF[wm * 256 + 128 + lane * 4];
            *(uint4*)&ual[0] = *(const uint4*)&AlF[wm * 256 + lane * 4];
            *(uint4*)&ual[4] = *(const uint4*)&AlF[wm * 256 + 128 + lane * 4];
            *(uint4*)&ubh[0] = *(const uint4*)&BhF[wn * 256 + lane * 4];
            *(uint4*)&ubh[4] = *(const uint4*)&BhF[wn * 256 + 128 + lane * 4];
            *(uint4*)&ubl[0] = *(const uint4*)&BlF[wn * 256 + lane * 4];
            *(uint4*)&ubl[4] = *(const uint4*)&BlF[wn * 256 + 128 + lane * 4];
#pragma unroll
            for (int mt = 0; mt < 2; mt++)
#pragma unroll
                for (int nt = 0; nt < 4; nt++) {
                    mma16(cf[mt][nt], &uah[mt * 4], &ubh[nt * 2]);
                    mma16(cf[mt][nt], &uah[mt * 4], &ubl[nt * 2]);
                    mma16(cf[mt][nt], &ual[mt * 4], &ubh[nt * 2]);
                }
        }
        __syncthreads();
    }

    if (md == 2) {
        float* Csm   = (float*)(smd + CS_OFF);   // [64][132]
        float* rel_s = (float*)(smd + RS_OFF);   // [2][2048]
        const float* rel2 = gb.rel2[b];
        for (int i = t; i < 4096; i += 256) rel_s[i] = rel2[i];
#pragma unroll
        for (int mt = 0; mt < 2; mt++)
#pragma unroll
            for (int half = 0; half < 2; half++) {
                int rl = wm * 32 + mt * 16 + half * 8 + g;
#pragma unroll
                for (int nt = 0; nt < 4; nt++) {
                    int col = wn * 32 + nt * 8 + c * 2;
                    float2 bb = *(const float2*)&bias[col];
                    Csm[rl * 132 + col]     = cf[mt][nt][half * 2 + 0] + bb.x;
                    Csm[rl * 132 + col + 1] = cf[mt][nt][half * 2 + 1] + bb.y;
                }
            }
        __syncthreads();

        int o2 = t & 63;
        int h = o2 >> 3, ep = (o2 & 7) * 2;
        __half* hout = gb.hout[b];
        const float* rb0 = &rel_s[h * 256 + ep];
        const float* rb1 = &rel_s[2048 + h * 256 + ep];
#pragma unroll 1
        for (int i = 0; i < 16; i++) {
            int nl = (t >> 6) + i * 4;
            int node = m0 + nl;
            if (node >= M) continue;
            const float* crow = &Csm[nl * 132 + h * 16];
            float4 c0 = *(const float4*)&crow[0];
            float4 c1 = *(const float4*)&crow[4];
            float4 c2 = *(const float4*)&crow[8];
            float4 c3 = *(const float4*)&crow[12];
#pragma unroll
            for (int ri = 0; ri < 2; ri++) {
                const float* rs = ri ? rb1 : rb0;
                u64 acc = 0ull;
                fma2(acc, pk2(c0.x), *(const u64*)&rs[0]);
                fma2(acc, pk2(c0.y), *(const u64*)&rs[16]);
                fma2(acc, pk2(c0.z), *(const u64*)&rs[32]);
                fma2(acc, pk2(c0.w), *(const u64*)&rs[48]);
                fma2(acc, pk2(c1.x), *(const u64*)&rs[64]);
                fma2(acc, pk2(c1.y), *(const u64*)&rs[80]);
                fma2(acc, pk2(c1.z), *(const u64*)&rs[96]);
                fma2(acc, pk2(c1.w), *(const u64*)&rs[112]);
                fma2(acc, pk2(c2.x), *(const u64*)&rs[128]);
                fma2(acc, pk2(c2.y), *(const u64*)&rs[144]);
                fma2(acc, pk2(c2.z), *(const u64*)&rs[160]);
                fma2(acc, pk2(c2.w), *(const u64*)&rs[176]);
                fma2(acc, pk2(c3.x), *(const u64*)&rs[192]);
                fma2(acc, pk2(c3.y), *(const u64*)&rs[208]);
                fma2(acc, pk2(c3.z), *(const u64*)&rs[224]);
                fma2(acc, pk2(c3.w), *(const u64*)&rs[240]);
                float2 res = up2(acc);
                *(__half2*)(hout + ((size_t)ri * NN + node) * 128 + h * 16 + ep) =
                    __floats2half2_rn(res.x, res.y);
            }
        }
        return;
    }

    float* C = gb.C[b];
    float al = 0.f, om = 0.f;
    if (md == 1) { al = 1.f / (1.f + __expf(-skip[b])); om = 1.f - al; }

#pragma unroll
    for (int mt = 0; mt < 2; mt++) {
        int rbase = m0 + wm * 32 + mt * 16 + g;
#pragma unroll
        for (int half = 0; half < 2; half++) {
            int row = rbase + half * 8;
            if (row >= M) continue;
#pragma unroll
            for (int nt = 0; nt < 4; nt++) {
                int col = wn * 32 + nt * 8 + c * 2;
                float v0 = cf[mt][nt][half * 2 + 0];
                float v1 = cf[mt][nt][half * 2 + 1];
                float2 bb = *(const float2*)&bias[col];
                float2 o;
                if (md == 0) {
                    o.x = v0 + bb.x; o.y = v1 + bb.y;
                } else {
                    float2 hr = *(const float2*)&gb.hres[b][(size_t)row * 128 + col];
                    o.x = al * (0.5f * v0 + bb.x) + om * hr.x;
                    o.y = al * (0.5f * v1 + bb.y) + om * hr.y;
                }
                *(float2*)&C[(size_t)row * 128 + col] = o;
            }
        }
    }
}

// ---------------------------------------------------------------------------
// Counting sort of edges by (relation, dst)
// ---------------------------------------------------------------------------
__global__ __launch_bounds__(256) void hist_kernel(Edges eg)
{
    int r = blockIdx.y;
    int e = blockIdx.x * 256 + threadIdx.x;
    int d = eg.dst[r][e];
    atomicAdd((int*)&g_s[OFF_CNT] + r * PAD + d, 1);
}

__global__ __launch_bounds__(256) void scanA_kernel()
{
    const int* cnt  = (const int*)&g_s[OFF_CNT];
    int*       offs = (int*)&g_s[OFF_OFFS];
    int*       blk  = (int*)&g_s[OFF_BLK];
    __shared__ int sm[256];
    int t = threadIdx.x;
    int base = (blockIdx.x * 256 + t) * 4;
    int c0 = cnt[base], c1 = cnt[base + 1], c2 = cnt[base + 2], c3 = cnt[base + 3];
    int tot = c0 + c1 + c2 + c3;
    sm[t] = tot;
    __syncthreads();
#pragma unroll
    for (int off = 1; off < 256; off <<= 1) {
        int u = (t >= off) ? sm[t - off] : 0;
        __syncthreads();
        sm[t] += u;
        __syncthreads();
    }
    int ex = sm[t] - tot;
    offs[base]     = ex;
    offs[base + 1] = ex + c0;
    offs[base + 2] = ex + c0 + c1;
    offs[base + 3] = ex + c0 + c1 + c2;
    if (t == 255) blk[blockIdx.x] = sm[255];
}

__global__ __launch_bounds__(256) void scanC_kernel()
{
    int* offs = (int*)&g_s[OFF_OFFS];
    int* cur  = (int*)&g_s[OFF_CUR];
    const int* blk = (const int*)&g_s[OFF_BLK];
    __shared__ int pre[128];
    int t = threadIdx.x;
    if (t < 128) pre[t] = (t < 80) ? blk[t] : 0;
    __syncthreads();
#pragma unroll
    for (int off = 1; off < 128; off <<= 1) {
        int u = (t < 128 && t >= off) ? pre[t - off] : 0;
        __syncthreads();
        if (t < 128) pre[t] += u;
        __syncthreads();
    }
    int i = blockIdx.x * 256 + t;
    int bidx = i >> 10;
    int add = (bidx == 0) ? 0 : pre[bidx - 1];
    int v = offs[i] + add;
    offs[i] = v;
    cur[i]  = v;
}

__global__ __launch_bounds__(256) void scatter_kernel(Edges eg)
{
    int r = blockIdx.y;
    int e = blockIdx.x * 256 + threadIdx.x;
    int d = eg.dst[r][e];
    int pos = atomicAdd((int*)&g_s[OFF_CUR] + r * PAD + d, 1);
    ((int*)&g_s[OFF_SRT])[pos] = eg.src[r][e];
}

// ---------------------------------------------------------------------------
// Fused score + softmax + aggregate (R13-verified version). One warp per
// (dst-type, node); fp16 k/v gathers (8B/lane), fp32 math, one STG.128.
// ---------------------------------------------------------------------------
__global__ __launch_bounds__(256) void attn_kernel(const float* __restrict__ pri)
{
    int warp = (blockIdx.x * 256 + threadIdx.x) >> 5;
    int lane = threadIdx.x & 31;
    int dt = warp / PAD;
    int d  = warp - dt * PAD;
    if (d >= NN) return;
    const int* offs = (const int*)&g_s[OFF_OFFS];
    const int* ss   = (const int*)&g_s[OFF_SRT];

    float4 q4 = *((const float4*)&g_s[OFF_Q + ((size_t)dt * NN + d) * 128] + lane);
    float4 tot = make_float4(0.f, 0.f, 0.f, 0.f);

#pragma unroll
    for (int half = 0; half < 2; half++) {
        int r   = dt + half * 2;
        int seg = r * PAD + d;
        int beg = offs[seg];
        int end = offs[seg + 1];
        if (beg == end) continue;

        float ph = pri[r * 8 + (lane >> 2)] * 0.25f;
        const __half* kbase = (const __half*)&g_s[OFF_K] + (size_t)r * NN * 128;
        const __half* vbase = (const __half*)&g_s[OFF_V] + (size_t)r * NN * 128;

        float4 acc = make_float4(0.f, 0.f, 0.f, 0.f);
        float ssum = 0.f;

        for (int c = beg; c < end; c += 32) {
            int m = end - c; if (m > 32) m = 32;
            int sl = ss[c + (lane < m ? lane : m - 1)];
            int s0 = __shfl_sync(0xffffffffu, sl, 0);
            uint2 kr = *(const uint2*)(kbase + (size_t)s0 * 128 + lane * 4);
            uint2 vr = *(const uint2*)(vbase + (size_t)s0 * 128 + lane * 4);
            for (int j = 0; j < m; j++) {
                uint2 ckr = kr, cvr = vr;
                if (j + 1 < m) {
                    int s2 = __shfl_sync(0xffffffffu, sl, j + 1);
                    kr = *(const uint2*)(kbase + (size_t)s2 * 128 + lane * 4);
                    vr = *(const uint2*)(vbase + (size_t)s2 * 128 + lane * 4);
                }
                float2 k01 = __half22float2(*(__half2*)&ckr.x);
                float2 k23 = __half22float2(*(__half2*)&ckr.y);
                float dot = k01.x * q4.x + k01.y * q4.y + k23.x * q4.z + k23.y * q4.w;
                dot += __shfl_xor_sync(0xffffffffu, dot, 1);
                dot += __shfl_xor_sync(0xffffffffu, dot, 2);
                float exv = __expf(dot * ph);
                ssum += exv;
                float2 v01 = __half22float2(*(__half2*)&cvr.x);
                float2 v23 = __half22float2(*(__half2*)&cvr.y);
                acc.x = fmaf(exv, v01.x, acc.x);
                acc.y = fmaf(exv, v01.y, acc.y);
                acc.z = fmaf(exv, v23.x, acc.z);
                acc.w = fmaf(exv, v23.y, acc.w);
            }
        }
        float inv = 1.f / ssum;
        tot.x = fmaf(acc.x, inv, tot.x);
        tot.y = fmaf(acc.y, inv, tot.y);
        tot.z = fmaf(acc.z, inv, tot.z);
        tot.w = fmaf(acc.w, inv, tot.w);
    }

    *(float4*)(&g_s[OFF_AGG + ((size_t)dt * NN + d) * 128] + lane * 4) = tot;
}

// ---------------------------------------------------------------------------
extern "C" void kernel_launch(void* const* d_in, const int* in_sizes, int n_in,
                              void* d_out, int out_size)
{
    const float* h_a  = (const float*)d_in[0];
    const float* h_b  = (const float*)d_in[1];
    const float* Wk   = (const float*)d_in[2];
    const float* bk   = (const float*)d_in[3];
    const float* Wq   = (const float*)d_in[4];
    const float* bq   = (const float*)d_in[5];
    const float* Wv   = (const float*)d_in[6];
    const float* bv   = (const float*)d_in[7];
    const float* Wa   = (const float*)d_in[8];
    const float* ba   = (const float*)d_in[9];
    const float* ratt = (const float*)d_in[10];
    const float* rmsg = (const float*)d_in[11];
    const float* rpri = (const float*)d_in[12];
    const float* skip = (const float*)d_in[13];
    float* out = (float*)d_out;

    float* base = nullptr;
    cudaGetSymbolAddress((void**)&base, g_s);
    __half* Kh = (__half*)(base + OFF_K);
    __half* Vh = (__half*)(base + OFF_V);

    cudaFuncSetAttribute(gemm_tc, cudaFuncAttributeMaxDynamicSharedMemorySize, SMEM_SZ);

    // one-time side stream + fork/join events
    static cudaStream_t s1 = nullptr;
    static cudaEvent_t evFork = nullptr, evJoin = nullptr;
    if (s1 == nullptr) {
        cudaStreamCreateWithFlags(&s1, cudaStreamNonBlocking);
        cudaEventCreateWithFlags(&evFork, cudaEventDisableTiming);
        cudaEventCreateWithFlags(&evJoin, cudaEventDisableTiming);
    }

    Edges eg;
    eg.src[0] = (const int*)d_in[14]; eg.dst[0] = (const int*)d_in[15];
    eg.src[1] = (const int*)d_in[16]; eg.dst[1] = (const int*)d_in[17];
    eg.src[2] = (const int*)d_in[18]; eg.dst[2] = (const int*)d_in[19];
    eg.src[3] = (const int*)d_in[20]; eg.dst[3] = (const int*)d_in[21];

    // --- fork: counting sort chain on side stream ---
    cudaEventRecord(evFork, 0);
    cudaStreamWaitEvent(s1, evFork, 0);
    cudaMemsetAsync(base + OFF_CNT, 0, (size_t)NSEG * sizeof(int), s1);
    dim3 egrid(EE / 256, 4);
    hist_kernel<<<egrid, 256, 0, s1>>>(eg);
    scanA_kernel<<<NSEG / 1024, 256, 0, s1>>>();
    scanC_kernel<<<NSEG / 256, 256, 0, s1>>>();
    scatter_kernel<<<egrid, 256, 0, s1>>>(eg);
    cudaEventRecord(evJoin, s1);

    // --- main stream: preconversions + projections ---
    wprep_kernel<<<dim3(8, 8), 256>>>(Wk, Wq, Wv, Wa);
    aprep_kernel<<<dim3(GMB, 8, 2), 256>>>(h_a, h_b);

    GemmBatch pj = {};
    pj.atype[0] = 0; pj.wm[0] = 2; pj.md[0] = 0; pj.bias[0] = bq;       pj.C[0] = base + OFF_Q;
    pj.atype[1] = 1; pj.wm[1] = 3; pj.md[1] = 0; pj.bias[1] = bq + 128; pj.C[1] = base + OFF_Q + S_NN;
    pj.atype[2] = 0; pj.wm[2] = 0; pj.md[2] = 2; pj.bias[2] = bk;       pj.rel2[2] = ratt;            pj.hout[2] = Kh;
    pj.atype[3] = 1; pj.wm[3] = 1; pj.md[3] = 2; pj.bias[3] = bk + 128; pj.rel2[3] = ratt + 2 * 2048; pj.hout[3] = Kh + (size_t)2 * NN * 128;
    pj.atype[4] = 0; pj.wm[4] = 4; pj.md[4] = 2; pj.bias[4] = bv;       pj.rel2[4] = rmsg;            pj.hout[4] = Vh;
    pj.atype[5] = 1; pj.wm[5] = 5; pj.md[5] = 2; pj.bias[5] = bv + 128; pj.rel2[5] = rmsg + 2 * 2048; pj.hout[5] = Vh + (size_t)2 * NN * 128;
    gemm_tc<<<dim3(GMB, 6), 256, SMEM_SZ>>>(pj, NN, nullptr);

    // --- join: attn needs sorted edges + q/k/v ---
    cudaStreamWaitEvent(0, evJoin, 0);
    attn_kernel<<<(2 * PAD) / 8, 256>>>(rpri);

    // --- batched output GEMMs with fused mean (0.5), bias, sigmoid skip ---
    GemmBatch og = {};
    og.A[0] = base + OFF_AGG;        og.atype[0] = -1; og.wm[0] = 6; og.md[0] = 1; og.bias[0] = ba;       og.C[0] = out;        og.hres[0] = h_a;
    og.A[1] = base + OFF_AGG + S_NN; og.atype[1] = -1; og.wm[1] = 7; og.md[1] = 1; og.bias[1] = ba + 128; og.C[1] = out + S_NN; og.hres[1] = h_b;
    gemm_tc<<<dim3(GMB, 2), 256, SMEM_SZ>>>(og, NN, skip);
}

// round 17
// speedup vs baseline: 1.5125x; 1.0295x over previous
#include <cuda_runtime.h>
#include <cuda_fp16.h>

#define NN 20000
#define EE 320000
#define PAD 20480              // padded per-relation segment count (80 * 256)
#define NSEG (4 * PAD)         // 81920 total segments
#define GMB 313                // GEMM M-blocks (64 rows each)

constexpr size_t S_NN   = (size_t)NN * 128;
constexpr size_t OFF_Q    = 0;                          // q_a, q_b           : 2*S_NN fp32
constexpr size_t OFF_K    = OFF_Q   + 2 * S_NN;         // k per relation fp16 (4 rel)
constexpr size_t OFF_V    = OFF_K   + 2 * S_NN;         // v per relation fp16
constexpr size_t OFF_SRT  = OFF_V   + 2 * S_NN;         // sorted src ids     : 4*EE
constexpr size_t OFF_OFFS = OFF_SRT + (size_t)4 * EE;   // segment offsets    : NSEG
constexpr size_t OFF_CUR  = OFF_OFFS + NSEG;            // scatter cursors    : NSEG
constexpr size_t OFF_BLK  = OFF_CUR  + NSEG;            // block partials     : 128
constexpr size_t OFF_CNT  = OFF_BLK  + 128;             // histogram          : NSEG
constexpr size_t OFF_AGG  = OFF_CNT  + NSEG;            // aggregates (a,b)   : 2*S_NN
constexpr size_t OFF_WS   = OFF_AGG + 2 * S_NN;         // preswizzled fp16 hi/lo W
constexpr size_t OFF_AP   = OFF_WS + (size_t)8 * 8 * 2048;  // preswizzled fp16 hi/lo A
constexpr size_t TOTAL    = OFF_AP + (size_t)2 * GMB * 8 * 1024;

__device__ __align__(256) float g_s[TOTAL];

typedef unsigned long long u64;
typedef unsigned int u32;

// dynamic smem layout (bytes)
#define AH_OFF 0
#define AL_OFF 2048
#define BH_OFF 4096
#define BL_OFF 8192
#define CS_OFF 12288           // 64 x 132 fp32 = 33792
#define RS_OFF 46080           // 2 x 2048 fp32 = 16384
#define SMEM_SZ 62464

__device__ __forceinline__ u64 pk2(float x) {
    u64 r; asm("mov.b64 %0, {%1, %1};" : "=l"(r) : "f"(x)); return r;
}
__device__ __forceinline__ void fma2(u64& d, u64 a, u64 b) {
    asm("fma.rn.f32x2 %0, %1, %2, %0;" : "+l"(d) : "l"(a), "l"(b));
}
__device__ __forceinline__ float2 up2(u64 v) {
    float2 f; asm("mov.b64 {%0, %1}, %2;" : "=f"(f.x), "=f"(f.y) : "l"(v)); return f;
}
__device__ __forceinline__ void mma16(float* c, const u32* a, const u32* b) {
    asm("mma.sync.aligned.m16n8k16.row.col.f32.f16.f16.f32 "
        "{%0,%1,%2,%3}, {%4,%5,%6,%7}, {%8,%9}, {%0,%1,%2,%3};"
        : "+f"(c[0]), "+f"(c[1]), "+f"(c[2]), "+f"(c[3])
        : "r"(a[0]), "r"(a[1]), "r"(a[2]), "r"(a[3]), "r"(b[0]), "r"(b[1]));
}

struct Edges { const int* src[4]; const int* dst[4]; };

struct GemmBatch {
    const float* A[6];        // used when atype < 0 (in-kernel split)
    int          atype[6];    // 0 = h_a pre, 1 = h_b pre, -1 = in-kernel
    int          wm[6];       // preswizzled weight index
    int          md[6];       // 0 = plain, 1 = skip-epilogue, 2 = relation-transform
    int          nt[6];       // compensation terms: 1 = hi*hi only, 3 = full
    const float* bias[6];
    float*       C[6];        // modes 0/1
    const float* hres[6];     // mode 1
    const float* rel2[6];     // mode 2: rel base for relations r0, r0+1
    __half*      hout[6];     // mode 2: fp16 out base for relation r0
};

// ---------------------------------------------------------------------------
// One-shot weight preconversion (fp16 hi/lo, m16n8k16 fragment layout).
// ---------------------------------------------------------------------------
__global__ __launch_bounds__(256) void wprep_kernel(
    const float* __restrict__ Wk, const float* __restrict__ Wq,
    const float* __restrict__ Wv, const float* __restrict__ Wa)
{
    const float* mats[8] = {Wk, Wk + 16384, Wq, Wq + 16384,
                            Wv, Wv + 16384, Wa, Wa + 16384};
    int mat = blockIdx.x, kc = blockIdx.y;
    const float* W = mats[mat];
    u32* dstH = (u32*)&g_s[OFF_WS] + (size_t)(mat * 8 + kc) * 2048;
    u32* dstL = dstH + 1024;

    int t = threadIdx.x;
    int bk = t >> 4;
    int bn8 = (t & 15) * 8;
    const float* wr = &W[(size_t)(kc * 16 + bk) * 128 + bn8];
    float4 w0 = *(const float4*)&wr[0];
    float4 w1 = *(const float4*)&wr[4];
    float wv[8] = {w0.x, w0.y, w0.z, w0.w, w1.x, w1.y, w1.z, w1.w};
    int c = (bk & 7) >> 1, hlf = bk & 1, reg = bk >> 3;
#pragma unroll
    for (int j = 0; j < 8; j++) {
        int n = bn8 + j;
        int wn = n >> 5, nt = (n >> 3) & 3, g = n & 7;
        int idx = nt * 2 + reg;
        int lane = g * 4 + c;
        int flat = wn * 256 + (idx >> 2) * 128 + lane * 4 + (idx & 3);
        float x = wv[j];
        __half hi = __float2half_rn(x);
        float lo = x - __half2float(hi);
        ((__half*)dstH)[flat * 2 + hlf] = hi;
        ((__half*)dstL)[flat * 2 + hlf] = __float2half_rn(lo);
    }
}

// ---------------------------------------------------------------------------
// One-shot A preconversion: h_a / h_b split to fp16 hi/lo in fragment layout.
// ---------------------------------------------------------------------------
__global__ __launch_bounds__(256) void aprep_kernel(
    const float* __restrict__ h_a, const float* __restrict__ h_b)
{
    __shared__ u32 buf[1024];
    int type = blockIdx.z, blk = blockIdx.x, kc = blockIdx.y;
    const float* src = type ? h_b : h_a;
    int t = threadIdx.x;
    int ar = t >> 2;
    int ac4 = (t & 3) * 4;
    int row = blk * 64 + ar;
    float4 va;
    if (row < NN) va = *(const float4*)&src[(size_t)row * 128 + kc * 16 + ac4];
    else          va = make_float4(0.f, 0.f, 0.f, 0.f);

    int awm = ar >> 5, amt = (ar >> 4) & 1, arh = (ar >> 3) & 1, agg = ar & 7;
    int khigh = ac4 >> 3, c0 = (ac4 & 7) >> 1;
    int areg = khigh * 2 + arh;
    int aidx = amt * 4 + areg;
    int lane0 = agg * 4 + c0;
    int f0 = awm * 256 + (aidx >> 2) * 128 + lane0 * 4 + (aidx & 3);
    int f1 = f0 + 4;

    __half2 h0 = __floats2half2_rn(va.x, va.y);
    float2 d0 = __half22float2(h0);
    __half2 l0 = __floats2half2_rn(va.x - d0.x, va.y - d0.y);
    __half2 h1 = __floats2half2_rn(va.z, va.w);
    float2 d1 = __half22float2(h1);
    __half2 l1 = __floats2half2_rn(va.z - d1.x, va.w - d1.y);
    buf[f0]       = *(u32*)&h0;
    buf[f1]       = *(u32*)&h1;
    buf[512 + f0] = *(u32*)&l0;
    buf[512 + f1] = *(u32*)&l1;
    __syncthreads();
    u32* dst = (u32*)&g_s[OFF_AP] + (((size_t)type * GMB + blk) * 8 + kc) * 1024;
    *(uint4*)&dst[t * 4] = *(const uint4*)&buf[t * 4];
}

// ---------------------------------------------------------------------------
// Tensor-core (M x 128)@(128 x 128) GEMM, fp16 MMA with configurable
// compensation (nt=3: hi*hi + hi*lo + lo*hi ; nt=1: hi*hi only).
// mode 0: C = A@W + bias
// mode 1: al = sigmoid(skip[b]); C = al*(0.5*A@W + bias) + (1-al)*hres
// mode 2: per-head 16x16 relation transform, fp16 output for relations r0,r0+1
// ---------------------------------------------------------------------------
__global__ __launch_bounds__(256, 2) void gemm_tc(
    GemmBatch gb, int M, const float* __restrict__ skip)
{
    extern __shared__ char smd[];
    u32* AhF = (u32*)(smd + AH_OFF);
    u32* AlF = (u32*)(smd + AL_OFF);
    u32* BhF = (u32*)(smd + BH_OFF);
    u32* BlF = (u32*)(smd + BL_OFF);

    int b = blockIdx.y;
    int md    = gb.md[b];
    int atype = gb.atype[b];
    bool full3 = (gb.nt[b] == 3);
    const float* __restrict__ bias = gb.bias[b];
    const u32*   __restrict__ Wsw  = (const u32*)&g_s[OFF_WS] +
                                     (size_t)gb.wm[b] * 8 * 2048;
    const u32*   __restrict__ Apre = (const u32*)&g_s[OFF_AP];

    int t    = threadIdx.x;
    int m0   = blockIdx.x * 64;
    int wid  = t >> 5;
    int lane = t & 31;
    int wm   = wid >> 2;
    int wn   = wid & 3;
    int g    = lane >> 2;
    int c    = lane & 3;

    float cf[2][4][4];
#pragma unroll
    for (int mt = 0; mt < 2; mt++)
#pragma unroll
        for (int nt = 0; nt < 4; nt++)
#pragma unroll
            for (int i = 0; i < 4; i++) cf[mt][nt][i] = 0.f;

    int ar = t >> 2;
    int ac4 = (t & 3) * 4;
    int t4 = t * 4;
    int awm = ar >> 5, amt = (ar >> 4) & 1, arh = (ar >> 3) & 1, agg = ar & 7;
    int khigh = ac4 >> 3, c0i = (ac4 & 7) >> 1;
    int areg = khigh * 2 + arh;
    int aidx = amt * 4 + areg;
    int fl0 = awm * 256 + (aidx >> 2) * 128 + (agg * 4 + c0i) * 4 + (aidx & 3);
    int fl1 = fl0 + 4;

    for (int kc = 0; kc < 8; kc++) {
        if (atype >= 0) {
            const u32* sA = Apre + (((size_t)atype * GMB + blockIdx.x) * 8 + kc) * 1024;
            *(uint2*)&AhF[t * 2] = *(const uint2*)&sA[t * 2];
            if (full3)
                *(uint2*)&AlF[t * 2] = *(const uint2*)&sA[512 + t * 2];
        } else {
            const float* A = gb.A[b];
            float4 va;
            if (m0 + ar < M) va = *(const float4*)&A[(size_t)(m0 + ar) * 128 + kc * 16 + ac4];
            else             va = make_float4(0.f, 0.f, 0.f, 0.f);
            __half2 h0 = __floats2half2_rn(va.x, va.y);
            float2 d0 = __half22float2(h0);
            __half2 l0 = __floats2half2_rn(va.x - d0.x, va.y - d0.y);
            __half2 h1 = __floats2half2_rn(va.z, va.w);
            float2 d1 = __half22float2(h1);
            __half2 l1 = __floats2half2_rn(va.z - d1.x, va.w - d1.y);
            AhF[fl0] = *(u32*)&h0;
            AhF[fl1] = *(u32*)&h1;
            AlF[fl0] = *(u32*)&l0;
            AlF[fl1] = *(u32*)&l1;
        }
        {
            const u32* srcH = Wsw + (size_t)kc * 2048;
            const u32* srcL = srcH + 1024;
            *(uint4*)&BhF[t4] = *(const uint4*)&srcH[t4];
            if (full3)
                *(uint4*)&BlF[t4] = *(const uint4*)&srcL[t4];
        }
        __syncthreads();

        {
            u32 uah[8], ubh[8];
            *(uint4*)&uah[0] = *(const uint4*)&AhF[wm * 256 + lane * 4];
            *(uint4*)&uah[4] = *(const uint4*)&AhF[wm * 256 + 128 + lane * 4];
            *(uint4*)&ubh[0] = *(const uint4*)&BhF[wn * 256 + lane * 4];
            *(uint4*)&ubh[4] = *(const uint4*)&BhF[wn * 256 + 128 + lane * 4];
            if (full3) {
                u32 ual[8], ubl[8];
                *(uint4*)&ual[0] = *(const uint4*)&AlF[wm * 256 + lane * 4];
                *(uint4*)&ual[4] = *(const uint4*)&AlF[wm * 256 + 128 + lane * 4];
                *(uint4*)&ubl[0] = *(const uint4*)&BlF[wn * 256 + lane * 4];
                *(uint4*)&ubl[4] = *(const uint4*)&BlF[wn * 256 + 128 + lane * 4];
#pragma unroll
                for (int mt = 0; mt < 2; mt++)
#pragma unroll
                    for (int nt = 0; nt < 4; nt++) {
                        mma16(cf[mt][nt], &uah[mt * 4], &ubh[nt * 2]);
                        mma16(cf[mt][nt], &uah[mt * 4], &ubl[nt * 2]);
                        mma16(cf[mt][nt], &ual[mt * 4], &ubh[nt * 2]);
                    }
            } else {
#pragma unroll
                for (int mt = 0; mt < 2; mt++)
#pragma unroll
                    for (int nt = 0; nt < 4; nt++)
                        mma16(cf[mt][nt], &uah[mt * 4], &ubh[nt * 2]);
            }
        }
        __syncthreads();
    }

    if (md == 2) {
        float* Csm   = (float*)(smd + CS_OFF);   // [64][132]
        float* rel_s = (float*)(smd + RS_OFF);   // [2][2048]
        const float* rel2 = gb.rel2[b];
        for (int i = t; i < 4096; i += 256) rel_s[i] = rel2[i];
#pragma unroll
        for (int mt = 0; mt < 2; mt++)
#pragma unroll
            for (int half = 0; half < 2; half++) {
                int rl = wm * 32 + mt * 16 + half * 8 + g;
#pragma unroll
                for (int nt = 0; nt < 4; nt++) {
                    int col = wn * 32 + nt * 8 + c * 2;
                    float2 bb = *(const float2*)&bias[col];
                    Csm[rl * 132 + col]     = cf[mt][nt][half * 2 + 0] + bb.x;
                    Csm[rl * 132 + col + 1] = cf[mt][nt][half * 2 + 1] + bb.y;
                }
            }
        __syncthreads();

        int o2 = t & 63;
        int h = o2 >> 3, ep = (o2 & 7) * 2;
        __half* hout = gb.hout[b];
        const float* rb0 = &rel_s[h * 256 + ep];
        const float* rb1 = &rel_s[2048 + h * 256 + ep];
#pragma unroll 1
        for (int i = 0; i < 16; i++) {
            int nl = (t >> 6) + i * 4;
            int node = m0 + nl;
            if (node >= M) continue;
            const float* crow = &Csm[nl * 132 + h * 16];
            float4 c0 = *(const float4*)&crow[0];
            float4 c1 = *(const float4*)&crow[4];
            float4 c2 = *(const float4*)&crow[8];
            float4 c3 = *(const float4*)&crow[12];
#pragma unroll
            for (int ri = 0; ri < 2; ri++) {
                const float* rs = ri ? rb1 : rb0;
                u64 acc = 0ull;
                fma2(acc, pk2(c0.x), *(const u64*)&rs[0]);
                fma2(acc, pk2(c0.y), *(const u64*)&rs[16]);
                fma2(acc, pk2(c0.z), *(const u64*)&rs[32]);
                fma2(acc, pk2(c0.w), *(const u64*)&rs[48]);
                fma2(acc, pk2(c1.x), *(const u64*)&rs[64]);
                fma2(acc, pk2(c1.y), *(const u64*)&rs[80]);
                fma2(acc, pk2(c1.z), *(const u64*)&rs[96]);
                fma2(acc, pk2(c1.w), *(const u64*)&rs[112]);
                fma2(acc, pk2(c2.x), *(const u64*)&rs[128]);
                fma2(acc, pk2(c2.y), *(const u64*)&rs[144]);
                fma2(acc, pk2(c2.z), *(const u64*)&rs[160]);
                fma2(acc, pk2(c2.w), *(const u64*)&rs[176]);
                fma2(acc, pk2(c3.x), *(const u64*)&rs[192]);
                fma2(acc, pk2(c3.y), *(const u64*)&rs[208]);
                fma2(acc, pk2(c3.z), *(const u64*)&rs[224]);
                fma2(acc, pk2(c3.w), *(const u64*)&rs[240]);
                float2 res = up2(acc);
                *(__half2*)(hout + ((size_t)ri * NN + node) * 128 + h * 16 + ep) =
                    __floats2half2_rn(res.x, res.y);
            }
        }
        return;
    }

    float* C = gb.C[b];
    float al = 0.f, om = 0.f;
    if (md == 1) { al = 1.f / (1.f + __expf(-skip[b])); om = 1.f - al; }

#pragma unroll
    for (int mt = 0; mt < 2; mt++) {
        int rbase = m0 + wm * 32 + mt * 16 + g;
#pragma unroll
        for (int half = 0; half < 2; half++) {
            int row = rbase + half * 8;
            if (row >= M) continue;
#pragma unroll
            for (int nt = 0; nt < 4; nt++) {
                int col = wn * 32 + nt * 8 + c * 2;
                float v0 = cf[mt][nt][half * 2 + 0];
                float v1 = cf[mt][nt][half * 2 + 1];
                float2 bb = *(const float2*)&bias[col];
                float2 o;
                if (md == 0) {
                    o.x = v0 + bb.x; o.y = v1 + bb.y;
                } else {
                    float2 hr = *(const float2*)&gb.hres[b][(size_t)row * 128 + col];
                    o.x = al * (0.5f * v0 + bb.x) + om * hr.x;
                    o.y = al * (0.5f * v1 + bb.y) + om * hr.y;
                }
                *(float2*)&C[(size_t)row * 128 + col] = o;
            }
        }
    }
}

// ---------------------------------------------------------------------------
// Counting sort of edges by (relation, dst)
// ---------------------------------------------------------------------------
__global__ __launch_bounds__(256) void hist_kernel(Edges eg)
{
    int r = blockIdx.y;
    int e = blockIdx.x * 256 + threadIdx.x;
    int d = eg.dst[r][e];
    atomicAdd((int*)&g_s[OFF_CNT] + r * PAD + d, 1);
}

__global__ __launch_bounds__(256) void scanA_kernel()
{
    const int* cnt  = (const int*)&g_s[OFF_CNT];
    int*       offs = (int*)&g_s[OFF_OFFS];
    int*       blk  = (int*)&g_s[OFF_BLK];
    __shared__ int sm[256];
    int t = threadIdx.x;
    int base = (blockIdx.x * 256 + t) * 4;
    int c0 = cnt[base], c1 = cnt[base + 1], c2 = cnt[base + 2], c3 = cnt[base + 3];
    int tot = c0 + c1 + c2 + c3;
    sm[t] = tot;
    __syncthreads();
#pragma unroll
    for (int off = 1; off < 256; off <<= 1) {
        int u = (t >= off) ? sm[t - off] : 0;
        __syncthreads();
        sm[t] += u;
        __syncthreads();
    }
    int ex = sm[t] - tot;
    offs[base]     = ex;
    offs[base + 1] = ex + c0;
    offs[base + 2] = ex + c0 + c1;
    offs[base + 3] = ex + c0 + c1 + c2;
    if (t == 255) blk[blockIdx.x] = sm[255];
}

__global__ __launch_bounds__(256) void scanC_kernel()
{
    int* offs = (int*)&g_s[OFF_OFFS];
    int* cur  = (int*)&g_s[OFF_CUR];
    const int* blk = (const int*)&g_s[OFF_BLK];
    __shared__ int pre[128];
    int t = threadIdx.x;
    if (t < 128) pre[t] = (t < 80) ? blk[t] : 0;
    __syncthreads();
#pragma unroll
    for (int off = 1; off < 128; off <<= 1) {
        int u = (t < 128 && t >= off) ? pre[t - off] : 0;
        __syncthreads();
        if (t < 128) pre[t] += u;
        __syncthreads();
    }
    int i = blockIdx.x * 256 + t;
    int bidx = i >> 10;
    int add = (bidx == 0) ? 0 : pre[bidx - 1];
    int v = offs[i] + add;
    offs[i] = v;
    cur[i]  = v;
}

__global__ __launch_bounds__(256) void scatter_kernel(Edges eg)
{
    int r = blockIdx.y;
    int e = blockIdx.x * 256 + threadIdx.x;
    int d = eg.dst[r][e];
    int pos = atomicAdd((int*)&g_s[OFF_CUR] + r * PAD + d, 1);
    ((int*)&g_s[OFF_SRT])[pos] = eg.src[r][e];
}

// ---------------------------------------------------------------------------
// Fused score + softmax + aggregate (R13-verified version). One warp per
// (dst-type, node); fp16 k/v gathers (8B/lane), fp32 math, one STG.128.
// ---------------------------------------------------------------------------
__global__ __launch_bounds__(256) void attn_kernel(const float* __restrict__ pri)
{
    int warp = (blockIdx.x * 256 + threadIdx.x) >> 5;
    int lane = threadIdx.x & 31;
    int dt = warp / PAD;
    int d  = warp - dt * PAD;
    if (d >= NN) return;
    const int* offs = (const int*)&g_s[OFF_OFFS];
    const int* ss   = (const int*)&g_s[OFF_SRT];

    float4 q4 = *((const float4*)&g_s[OFF_Q + ((size_t)dt * NN + d) * 128] + lane);
    float4 tot = make_float4(0.f, 0.f, 0.f, 0.f);

#pragma unroll
    for (int half = 0; half < 2; half++) {
        int r   = dt + half * 2;
        int seg = r * PAD + d;
        int beg = offs[seg];
        int end = offs[seg + 1];
        if (beg == end) continue;

        float ph = pri[r * 8 + (lane >> 2)] * 0.25f;
        const __half* kbase = (const __half*)&g_s[OFF_K] + (size_t)r * NN * 128;
        const __half* vbase = (const __half*)&g_s[OFF_V] + (size_t)r * NN * 128;

        float4 acc = make_float4(0.f, 0.f, 0.f, 0.f);
        float ssum = 0.f;

        for (int c = beg; c < end; c += 32) {
            int m = end - c; if (m > 32) m = 32;
            int sl = ss[c + (lane < m ? lane : m - 1)];
            int s0 = __shfl_sync(0xffffffffu, sl, 0);
            uint2 kr = *(const uint2*)(kbase + (size_t)s0 * 128 + lane * 4);
            uint2 vr = *(const uint2*)(vbase + (size_t)s0 * 128 + lane * 4);
            for (int j = 0; j < m; j++) {
                uint2 ckr = kr, cvr = vr;
                if (j + 1 < m) {
                    int s2 = __shfl_sync(0xffffffffu, sl, j + 1);
                    kr = *(const uint2*)(kbase + (size_t)s2 * 128 + lane * 4);
                    vr = *(const uint2*)(vbase + (size_t)s2 * 128 + lane * 4);
                }
                float2 k01 = __half22float2(*(__half2*)&ckr.x);
                float2 k23 = __half22float2(*(__half2*)&ckr.y);
                float dot = k01.x * q4.x + k01.y * q4.y + k23.x * q4.z + k23.y * q4.w;
                dot += __shfl_xor_sync(0xffffffffu, dot, 1);
                dot += __shfl_xor_sync(0xffffffffu, dot, 2);
                float exv = __expf(dot * ph);
                ssum += exv;
                float2 v01 = __half22float2(*(__half2*)&cvr.x);
                float2 v23 = __half22float2(*(__half2*)&cvr.y);
                acc.x = fmaf(exv, v01.x, acc.x);
                acc.y = fmaf(exv, v01.y, acc.y);
                acc.z = fmaf(exv, v23.x, acc.z);
                acc.w = fmaf(exv, v23.y, acc.w);
            }
        }
        float inv = 1.f / ssum;
        tot.x = fmaf(acc.x, inv, tot.x);
        tot.y = fmaf(acc.y, inv, tot.y);
        tot.z = fmaf(acc.z, inv, tot.z);
        tot.w = fmaf(acc.w, inv, tot.w);
    }

    *(float4*)(&g_s[OFF_AGG + ((size_t)dt * NN + d) * 128] + lane * 4) = tot;
}

// ---------------------------------------------------------------------------
extern "C" void kernel_launch(void* const* d_in, const int* in_sizes, int n_in,
                              void* d_out, int out_size)
{
    const float* h_a  = (const float*)d_in[0];
    const float* h_b  = (const float*)d_in[1];
    const float* Wk   = (const float*)d_in[2];
    const float* bk   = (const float*)d_in[3];
    const float* Wq   = (const float*)d_in[4];
    const float* bq   = (const float*)d_in[5];
    const float* Wv   = (const float*)d_in[6];
    const float* bv   = (const float*)d_in[7];
    const float* Wa   = (const float*)d_in[8];
    const float* ba   = (const float*)d_in[9];
    const float* ratt = (const float*)d_in[10];
    const float* rmsg = (const float*)d_in[11];
    const float* rpri = (const float*)d_in[12];
    const float* skip = (const float*)d_in[13];
    float* out = (float*)d_out;

    float* base = nullptr;
    cudaGetSymbolAddress((void**)&base, g_s);
    __half* Kh = (__half*)(base + OFF_K);
    __half* Vh = (__half*)(base + OFF_V);

    cudaFuncSetAttribute(gemm_tc, cudaFuncAttributeMaxDynamicSharedMemorySize, SMEM_SZ);

    // one-time side stream + fork/join events
    static cudaStream_t s1 = nullptr;
    static cudaEvent_t evFork = nullptr, evJoin = nullptr;
    if (s1 == nullptr) {
        cudaStreamCreateWithFlags(&s1, cudaStreamNonBlocking);
        cudaEventCreateWithFlags(&evFork, cudaEventDisableTiming);
        cudaEventCreateWithFlags(&evJoin, cudaEventDisableTiming);
    }

    Edges eg;
    eg.src[0] = (const int*)d_in[14]; eg.dst[0] = (const int*)d_in[15];
    eg.src[1] = (const int*)d_in[16]; eg.dst[1] = (const int*)d_in[17];
    eg.src[2] = (const int*)d_in[18]; eg.dst[2] = (const int*)d_in[19];
    eg.src[3] = (const int*)d_in[20]; eg.dst[3] = (const int*)d_in[21];

    // --- fork: counting sort chain on side stream ---
    cudaEventRecord(evFork, 0);
    cudaStreamWaitEvent(s1, evFork, 0);
    cudaMemsetAsync(base + OFF_CNT, 0, (size_t)NSEG * sizeof(int), s1);
    dim3 egrid(EE / 256, 4);
    hist_kernel<<<egrid, 256, 0, s1>>>(eg);
    scanA_kernel<<<NSEG / 1024, 256, 0, s1>>>();
    scanC_kernel<<<NSEG / 256, 256, 0, s1>>>();
    scatter_kernel<<<egrid, 256, 0, s1>>>(eg);
    cudaEventRecord(evJoin, s1);

    // --- main stream: preconversions + projections ---
    wprep_kernel<<<dim3(8, 8), 256>>>(Wk, Wq, Wv, Wa);
    aprep_kernel<<<dim3(GMB, 8, 2), 256>>>(h_a, h_b);

    GemmBatch pj = {};
    pj.atype[0] = 0; pj.wm[0] = 2; pj.md[0] = 0; pj.nt[0] = 1; pj.bias[0] = bq;       pj.C[0] = base + OFF_Q;
    pj.atype[1] = 1; pj.wm[1] = 3; pj.md[1] = 0; pj.nt[1] = 1; pj.bias[1] = bq + 128; pj.C[1] = base + OFF_Q + S_NN;
    pj.atype[2] = 0; pj.wm[2] = 0; pj.md[2] = 2; pj.nt[2] = 1; pj.bias[2] = bk;       pj.rel2[2] = ratt;            pj.hout[2] = Kh;
    pj.atype[3] = 1; pj.wm[3] = 1; pj.md[3] = 2; pj.nt[3] = 1; pj.bias[3] = bk + 128; pj.rel2[3] = ratt + 2 * 2048; pj.hout[3] = Kh + (size_t)2 * NN * 128;
    pj.atype[4] = 0; pj.wm[4] = 4; pj.md[4] = 2; pj.nt[4] = 1; pj.bias[4] = bv;       pj.rel2[4] = rmsg;            pj.hout[4] = Vh;
    pj.atype[5] = 1; pj.wm[5] = 5; pj.md[5] = 2; pj.nt[5] = 1; pj.bias[5] = bv + 128; pj.rel2[5] = rmsg + 2 * 2048; pj.hout[5] = Vh + (size_t)2 * NN * 128;
    gemm_tc<<<dim3(GMB, 6), 256, SMEM_SZ>>>(pj, NN, nullptr);

    // --- join: attn needs sorted edges + q/k/v ---
    cudaStreamWaitEvent(0, evJoin, 0);
    attn_kernel<<<(2 * PAD) / 8, 256>>>(rpri);

    // --- batched output GEMMs with fused mean (0.5), bias, sigmoid skip ---
    GemmBatch og = {};
    og.A[0] = base + OFF_AGG;        og.atype[0] = -1; og.wm[0] = 6; og.md[0] = 1; og.nt[0] = 3; og.bias[0] = ba;       og.C[0] = out;        og.hres[0] = h_a;
    og.A[1] = base + OFF_AGG + S_NN; og.atype[1] = -1; og.wm[1] = 7; og.md[1] = 1; og.nt[1] = 3; og.bias[1] = ba + 128; og.C[1] = out + S_NN; og.hres[1] = h_b;
    gemm_tc<<<dim3(GMB, 2), 256, SMEM_SZ>>>(og, NN, skip);
}